// round 11
// baseline (speedup 1.0000x reference)
#include <cuda_runtime.h>
#include <cuda_bf16.h>
#include <cuda_fp16.h>
#include <cstdint>

#define SEQ 2048
#define HD  128
#define BM  128
#define BN  64
#define NTH 256          // 4 consumer warps + 4 producer warps
#define NCONS 128
#define ITERS (SEQ / BN)

// ring: 2 stages x (KHI,KLO bf16 + VH fp16) 16KB each = 48KB/stage
#define TILE_B  16384
#define STAGE_B (3 * TILE_B)
#define SM_QHI  (2 * STAGE_B)          // 98304
#define SM_QLO  (SM_QHI + 32768)       // 131072
#define SMEM_BYTES (SM_QLO + 32768)    // 163840

#define MAX_SLACK 6.0f   // rescale only when tile max exceeds m_used + slack

// swizzled byte offset of (row, d) in a tile with 256B rows (16-bit, 128 cols)
__device__ __forceinline__ uint32_t swz(int row, int d) {
    return ((uint32_t)row << 8) + ((((uint32_t)(d >> 3)) ^ (row & 7)) << 4) + (d & 7) * 2;
}

__device__ __forceinline__ uint32_t prmt_hi(float a, float b) {
    uint32_t r;
    asm("prmt.b32 %0, %1, %2, 0x7632;" : "=r"(r)
        : "r"(__float_as_uint(a)), "r"(__float_as_uint(b)));
    return r;
}
__device__ __forceinline__ uint32_t pack_lo(float a, float b) {
    float la = a - __uint_as_float(__float_as_uint(a) & 0xffff0000u);
    float lb = b - __uint_as_float(__float_as_uint(b) & 0xffff0000u);
    uint32_t r;
    asm("cvt.rn.bf16x2.f32 %0, %1, %2;" : "=r"(r) : "f"(lb), "f"(la));  // low = la
    return r;
}
__device__ __forceinline__ uint32_t pack_h2(float a, float b) {
    __half2 h = __floats2half2_rn(a, b);   // low = a
    return *(uint32_t*)&h;
}

__device__ __forceinline__ void mma16816(float* c, const uint32_t* a, uint32_t b0, uint32_t b1) {
    asm volatile(
        "mma.sync.aligned.m16n8k16.row.col.f32.bf16.bf16.f32 "
        "{%0,%1,%2,%3}, {%4,%5,%6,%7}, {%8,%9}, {%0,%1,%2,%3};"
        : "+f"(c[0]), "+f"(c[1]), "+f"(c[2]), "+f"(c[3])
        : "r"(a[0]), "r"(a[1]), "r"(a[2]), "r"(a[3]), "r"(b0), "r"(b1));
}
__device__ __forceinline__ void mma16816h(float* c, const uint32_t* a, uint32_t b0, uint32_t b1) {
    asm volatile(
        "mma.sync.aligned.m16n8k16.row.col.f32.f16.f16.f32 "
        "{%0,%1,%2,%3}, {%4,%5,%6,%7}, {%8,%9}, {%0,%1,%2,%3};"
        : "+f"(c[0]), "+f"(c[1]), "+f"(c[2]), "+f"(c[3])
        : "r"(a[0]), "r"(a[1]), "r"(a[2]), "r"(a[3]), "r"(b0), "r"(b1));
}
__device__ __forceinline__ void ldmx4(uint32_t* r, uint32_t addr) {
    asm volatile("ldmatrix.sync.aligned.m8n8.x4.shared.b16 {%0,%1,%2,%3}, [%4];"
                 : "=r"(r[0]), "=r"(r[1]), "=r"(r[2]), "=r"(r[3]) : "r"(addr));
}
__device__ __forceinline__ void ldmx4t(uint32_t* r, uint32_t addr) {
    asm volatile("ldmatrix.sync.aligned.m8n8.x4.trans.shared.b16 {%0,%1,%2,%3}, [%4];"
                 : "=r"(r[0]), "=r"(r[1]), "=r"(r[2]), "=r"(r[3]) : "r"(addr));
}
__device__ __forceinline__ void sts2(uint32_t addr, uint32_t x, uint32_t y) {
    asm volatile("st.shared.v2.b32 [%0], {%1, %2};" :: "r"(addr), "r"(x), "r"(y) : "memory");
}
__device__ __forceinline__ uint32_t smem_u32(const void* p) {
    uint32_t a;
    asm("{ .reg .u64 t; cvta.to.shared.u64 t, %1; cvt.u32.u64 %0, t; }" : "=r"(a) : "l"(p));
    return a;
}
__device__ __forceinline__ void mbar_init(uint32_t m, uint32_t cnt) {
    asm volatile("mbarrier.init.shared.b64 [%0], %1;" :: "r"(m), "r"(cnt) : "memory");
}
__device__ __forceinline__ void mbar_arrive(uint32_t m) {
    asm volatile("mbarrier.arrive.shared.b64 _, [%0];" :: "r"(m) : "memory");
}
__device__ __forceinline__ void mbar_wait(uint32_t m, uint32_t parity) {
    uint32_t done;
    asm volatile("{\n\t.reg .pred p;\n\t"
                 "mbarrier.try_wait.parity.acquire.cta.shared::cta.b64 p, [%1], %2;\n\t"
                 "selp.b32 %0, 1, 0, p;\n\t}"
                 : "=r"(done) : "r"(m), "r"(parity) : "memory");
    while (!done) {
        asm volatile("{\n\t.reg .pred p;\n\t"
                     "mbarrier.try_wait.parity.acquire.cta.shared::cta.b64 p, [%1], %2, 0x989680;\n\t"
                     "selp.b32 %0, 1, 0, p;\n\t}"
                     : "=r"(done) : "r"(m), "r"(parity) : "memory");
    }
}

__global__ void __launch_bounds__(NTH, 1)
adaptive_attn_ws(const float* __restrict__ q,
                 const float* __restrict__ k,
                 const float* __restrict__ v,
                 const float* __restrict__ alpha_p,
                 float* __restrict__ out) {
    extern __shared__ char smem[];
    __shared__ alignas(8) unsigned long long mbars[4];  // full0, full1, empty0, empty1
    const uint32_t sb = smem_u32(smem);
    const uint32_t mb = smem_u32(mbars);

    const int tid = threadIdx.x;
    const int qt = blockIdx.x;
    const int bh = blockIdx.y;
    const float av = alpha_p[0];

    const float* qg = q + ((long)bh * SEQ + (long)qt * BM) * HD;
    const float* kg = k + (long)bh * SEQ * HD;
    const float* vg = v + (long)bh * SEQ * HD;

    if (tid == 0) {
        mbar_init(mb + 0, 128);  // full[0]  : 128 producer threads
        mbar_init(mb + 8, 128);  // full[1]
        mbar_init(mb + 16, 4);   // empty[0] : 4 consumer warps (lane 0)
        mbar_init(mb + 24, 4);   // empty[1]
    }

    // ---- prologue: Q (alpha folded) -> bf16 hi/lo swizzled smem, all threads ----
    for (int idx = tid; idx < BM * HD / 4; idx += NTH) {
        int r = idx >> 5;
        int d = (idx & 31) << 2;
        float4 x = *(const float4*)(qg + r * HD + d);
        x.x *= av; x.y *= av; x.z *= av; x.w *= av;
        uint32_t off = swz(r, d);
        sts2(sb + SM_QHI + off, prmt_hi(x.x, x.y), prmt_hi(x.z, x.w));
        sts2(sb + SM_QLO + off, pack_lo(x.x, x.y), pack_lo(x.z, x.w));
    }
    __syncthreads();

    if (tid >= NCONS) {
        // ================= PRODUCER (warps 4-7) =================
        const int pt = tid - NCONS;  // 0..127
        uint32_t pe = 1;             // empty-wait phase (first pass free)
        for (int i = 0; i < ITERS; ++i) {
            const int s = i & 1;
            mbar_wait(mb + 16 + 8 * s, pe);
            const uint32_t base = sb + (uint32_t)s * STAGE_B;
            const float* kp = kg + (long)i * BN * HD;
            const float* vp = vg + (long)i * BN * HD;
            float4 xb[8];
#pragma unroll
            for (int h = 0; h < 2; ++h) {
#pragma unroll
                for (int t = 0; t < 8; ++t) {
                    int idx = pt + (h * 8 + t) * 128;
                    xb[t] = *(const float4*)(kp + (idx >> 5) * HD + ((idx & 31) << 2));
                }
#pragma unroll
                for (int t = 0; t < 8; ++t) {
                    int idx = pt + (h * 8 + t) * 128;
                    uint32_t off = swz(idx >> 5, (idx & 31) << 2);
                    sts2(base + off, prmt_hi(xb[t].x, xb[t].y), prmt_hi(xb[t].z, xb[t].w));
                    sts2(base + TILE_B + off, pack_lo(xb[t].x, xb[t].y), pack_lo(xb[t].z, xb[t].w));
                }
            }
            // V: single fp16 tile
#pragma unroll
            for (int h = 0; h < 2; ++h) {
#pragma unroll
                for (int t = 0; t < 8; ++t) {
                    int idx = pt + (h * 8 + t) * 128;
                    xb[t] = *(const float4*)(vp + (idx >> 5) * HD + ((idx & 31) << 2));
                }
#pragma unroll
                for (int t = 0; t < 8; ++t) {
                    int idx = pt + (h * 8 + t) * 128;
                    uint32_t off = swz(idx >> 5, (idx & 31) << 2);
                    sts2(base + 2 * TILE_B + off, pack_h2(xb[t].x, xb[t].y), pack_h2(xb[t].z, xb[t].w));
                }
            }
            mbar_arrive(mb + 8 * s);  // full[s]
            if (s == 1) pe ^= 1;
        }
        return;
    }

    // ================= CONSUMER (warps 0-3, 32 rows each) =================
    const int w = tid >> 5;
    const int lane = tid & 31;
    const int qq = lane & 3;
    const int jj = lane & 7;
    const int g = lane >> 3;
    const int rowadd = jj + ((g >> 1) << 3);        // B-operand ldmatrix row offset
    const int csel = g & 1;                         // B-operand chunk offset
    const int arow = w * 32 + ((g & 1) << 3) + jj;  // A-operand ldmatrix row (mt0)
    const int asel = g >> 1;                        // A-operand 8-col block
    const int row0 = w * 32 + (lane >> 2);          // rows row0, +8, +16, +24

    float oacc0[16][4], oacc1[16][4];               // mt0 (rows 0-15), mt1 (rows 16-31)
#pragma unroll
    for (int i = 0; i < 16; ++i)
#pragma unroll
        for (int e = 0; e < 4; ++e) { oacc0[i][e] = 0.0f; oacc1[i][e] = 0.0f; }
    float rs[4] = {0.0f, 0.0f, 0.0f, 0.0f};
    float m[4] = {-1e30f, -1e30f, -1e30f, -1e30f};  // lazy row maxes
    uint32_t pf = 0;

    const uint32_t qhi_b = sb + SM_QHI;
    const uint32_t qlo_b = sb + SM_QLO;

    for (int i = 0; i < ITERS; ++i) {
        const int s = i & 1;
        mbar_wait(mb + 8 * s, pf);
        const uint32_t base = sb + (uint32_t)s * STAGE_B;
        const uint32_t khi = base, klo = base + TILE_B;
        const uint32_t vh = base + 2 * TILE_B;

        // ---- S = (alpha Q) K^T, bf16x3; two M-tiles per warp ----
        float sf0[8][4], sf1[8][4];
#pragma unroll
        for (int nt = 0; nt < 8; ++nt)
#pragma unroll
            for (int e = 0; e < 4; ++e) { sf0[nt][e] = 0.0f; sf1[nt][e] = 0.0f; }

#pragma unroll
        for (int kk = 0; kk < 8; ++kk) {
            uint32_t qh0[4], ql0[4], qh1[4], ql1[4];
            uint32_t aoff = ((uint32_t)arow << 8) + ((((kk << 1) | asel) ^ jj) << 4);
            ldmx4(qh0, qhi_b + aoff);
            ldmx4(ql0, qlo_b + aoff);
            ldmx4(qh1, qhi_b + aoff + (16 << 8));
            ldmx4(ql1, qlo_b + aoff + (16 << 8));
#pragma unroll
            for (int np = 0; np < 4; ++np) {
                uint32_t off = ((uint32_t)(np * 16 + rowadd) << 8)
                             + ((((kk << 1) | csel) ^ jj) << 4);
                uint32_t bh4[4], bl4[4];
                ldmx4(bh4, khi + off);
                ldmx4(bl4, klo + off);
                mma16816(sf0[2 * np],     qh0, bh4[0], bh4[1]);
                mma16816(sf0[2 * np],     qh0, bl4[0], bl4[1]);
                mma16816(sf0[2 * np],     ql0, bh4[0], bh4[1]);
                mma16816(sf0[2 * np + 1], qh0, bh4[2], bh4[3]);
                mma16816(sf0[2 * np + 1], qh0, bl4[2], bl4[3]);
                mma16816(sf0[2 * np + 1], ql0, bh4[2], bh4[3]);
                mma16816(sf1[2 * np],     qh1, bh4[0], bh4[1]);
                mma16816(sf1[2 * np],     qh1, bl4[0], bl4[1]);
                mma16816(sf1[2 * np],     ql1, bh4[0], bh4[1]);
                mma16816(sf1[2 * np + 1], qh1, bh4[2], bh4[3]);
                mma16816(sf1[2 * np + 1], qh1, bl4[2], bl4[3]);
                mma16816(sf1[2 * np + 1], ql1, bh4[2], bh4[3]);
            }
        }

        // ---- lazy max (4 row groups) ----
        float tm[4];
        tm[0] = sf0[0][0]; tm[1] = sf0[0][2]; tm[2] = sf1[0][0]; tm[3] = sf1[0][2];
#pragma unroll
        for (int nt = 0; nt < 8; ++nt) {
            tm[0] = fmaxf(tm[0], fmaxf(sf0[nt][0], sf0[nt][1]));
            tm[1] = fmaxf(tm[1], fmaxf(sf0[nt][2], sf0[nt][3]));
            tm[2] = fmaxf(tm[2], fmaxf(sf1[nt][0], sf1[nt][1]));
            tm[3] = fmaxf(tm[3], fmaxf(sf1[nt][2], sf1[nt][3]));
        }
#pragma unroll
        for (int t = 0; t < 4; ++t) {
            tm[t] = fmaxf(tm[t], __shfl_xor_sync(0xffffffffu, tm[t], 1));
            tm[t] = fmaxf(tm[t], __shfl_xor_sync(0xffffffffu, tm[t], 2));
        }
        bool trig = false;
#pragma unroll
        for (int t = 0; t < 4; ++t) trig = trig || (tm[t] > m[t] + MAX_SLACK);
        if (__ballot_sync(0xffffffffu, trig)) {
            float sc[4];
#pragma unroll
            for (int t = 0; t < 4; ++t) {
                float mn = fmaxf(m[t], tm[t]);
                sc[t] = __expf(m[t] - mn);
                m[t] = mn;
                rs[t] *= sc[t];
            }
#pragma unroll
            for (int dt = 0; dt < 16; ++dt) {
                oacc0[dt][0] *= sc[0]; oacc0[dt][1] *= sc[0];
                oacc0[dt][2] *= sc[1]; oacc0[dt][3] *= sc[1];
                oacc1[dt][0] *= sc[2]; oacc1[dt][1] *= sc[2];
                oacc1[dt][2] *= sc[3]; oacc1[dt][3] *= sc[3];
            }
        }

        // ---- per 16-col chunk: exp in fp16, PV; V frags shared by both M-tiles ----
#pragma unroll
        for (int kk = 0; kk < 4; ++kk) {
            uint32_t p0[4], p1[4];
            {
                float a00 = __expf(sf0[2 * kk][0] - m[0]);
                float a01 = __expf(sf0[2 * kk][1] - m[0]);
                float a02 = __expf(sf0[2 * kk][2] - m[1]);
                float a03 = __expf(sf0[2 * kk][3] - m[1]);
                float a10 = __expf(sf0[2 * kk + 1][0] - m[0]);
                float a11 = __expf(sf0[2 * kk + 1][1] - m[0]);
                float a12 = __expf(sf0[2 * kk + 1][2] - m[1]);
                float a13 = __expf(sf0[2 * kk + 1][3] - m[1]);
                rs[0] += a00 + a01 + a10 + a11;
                rs[1] += a02 + a03 + a12 + a13;
                p0[0] = pack_h2(a00, a01); p0[1] = pack_h2(a02, a03);
                p0[2] = pack_h2(a10, a11); p0[3] = pack_h2(a12, a13);
            }
            {
                float a00 = __expf(sf1[2 * kk][0] - m[2]);
                float a01 = __expf(sf1[2 * kk][1] - m[2]);
                float a02 = __expf(sf1[2 * kk][2] - m[3]);
                float a03 = __expf(sf1[2 * kk][3] - m[3]);
                float a10 = __expf(sf1[2 * kk + 1][0] - m[2]);
                float a11 = __expf(sf1[2 * kk + 1][1] - m[2]);
                float a12 = __expf(sf1[2 * kk + 1][2] - m[3]);
                float a13 = __expf(sf1[2 * kk + 1][3] - m[3]);
                rs[2] += a00 + a01 + a10 + a11;
                rs[3] += a02 + a03 + a12 + a13;
                p1[0] = pack_h2(a00, a01); p1[1] = pack_h2(a02, a03);
                p1[2] = pack_h2(a10, a11); p1[3] = pack_h2(a12, a13);
            }
#pragma unroll
            for (int dp = 0; dp < 8; ++dp) {
                uint32_t off = ((uint32_t)(kk * 16 + rowadd) << 8)
                             + ((((dp << 1) | csel) ^ jj) << 4);
                uint32_t bv[4];
                ldmx4t(bv, vh + off);
                mma16816h(oacc0[2 * dp],     p0, bv[0], bv[2]);
                mma16816h(oacc0[2 * dp + 1], p0, bv[1], bv[3]);
                mma16816h(oacc1[2 * dp],     p1, bv[0], bv[2]);
                mma16816h(oacc1[2 * dp + 1], p1, bv[1], bv[3]);
            }
        }

        if (lane == 0) mbar_arrive(mb + 16 + 8 * s);  // empty[s]
        if (s == 1) pf ^= 1;
    }

    // ---- normalize + store ----
#pragma unroll
    for (int t = 0; t < 4; ++t) {
        rs[t] += __shfl_xor_sync(0xffffffffu, rs[t], 1);
        rs[t] += __shfl_xor_sync(0xffffffffu, rs[t], 2);
        rs[t] = 1.0f / rs[t];
    }

    float* og = out + ((long)bh * SEQ + (long)qt * BM + row0) * HD;
#pragma unroll
    for (int dt = 0; dt < 16; ++dt) {
        int c = dt * 8 + qq * 2;
        float2 x;
        x.x = oacc0[dt][0] * rs[0]; x.y = oacc0[dt][1] * rs[0];
        *(float2*)(og + c) = x;
        x.x = oacc0[dt][2] * rs[1]; x.y = oacc0[dt][3] * rs[1];
        *(float2*)(og + 8 * HD + c) = x;
        x.x = oacc1[dt][0] * rs[2]; x.y = oacc1[dt][1] * rs[2];
        *(float2*)(og + 16 * HD + c) = x;
        x.x = oacc1[dt][2] * rs[3]; x.y = oacc1[dt][3] * rs[3];
        *(float2*)(og + 24 * HD + c) = x;
    }
}

extern "C" void kernel_launch(void* const* d_in, const int* in_sizes, int n_in,
                              void* d_out, int out_size) {
    const float* q = (const float*)d_in[0];
    const float* k = (const float*)d_in[1];
    const float* v = (const float*)d_in[2];
    const float* alpha = (const float*)d_in[3];
    float* out = (float*)d_out;

    int bh = in_sizes[0] / (SEQ * HD);  // B*H = 32

    cudaFuncSetAttribute(adaptive_attn_ws,
                         cudaFuncAttributeMaxDynamicSharedMemorySize, SMEM_BYTES);

    dim3 grid(SEQ / BM, bh);
    adaptive_attn_ws<<<grid, NTH, SMEM_BYTES>>>(q, k, v, alpha, out);
}